// round 14
// baseline (speedup 1.0000x reference)
#include <cuda_runtime.h>
#include <cuda_fp16.h>
#include <mma.h>
#include <cstdint>

using namespace nvcuda;

#define N_NODES 10000
#define N_PAD   10240          // 20 * 512
#define GY      20             // row groups in GEMM grid
#define N_EDGES 65536
#define CIN1    16
#define HID     64

// ---- static device scratch (no allocations allowed) ----
__device__ __half g_Gh[(size_t)N_PAD * 4096];      // per-node factor, fp16 (84 MB)
__device__ __half g_Xh[N_PAD * 64];                // fp16 split of node features
__device__ __half g_Xl[N_PAD * 64];
__device__ __half g_Bh[64 * 4096];                 // fp16 split of permuted W2
__device__ __half g_Bl[64 * 4096];
__device__ __half g_h[(size_t)N_EDGES * 64];       // edge-MLP hidden (fp16)
__device__ float  g_XB[N_NODES * 64];              // bias-path per node
__device__ float  g_agg[N_NODES * 64];             // scatter accumulator
__device__ float  g_y[N_NODES * 64];               // layer-1 output
__device__ float  g_z[N_NODES * 64];               // layer-2 output
__device__ float  g_deg[N_NODES];                  // in-degree (by dst)

// ---- edge sort-by-src scratch ----
__device__ int g_cnt[N_NODES];
__device__ int g_off[N_NODES];
__device__ int g_cur[N_NODES];
__device__ int g_se[N_EDGES];                      // sorted edge id
__device__ int g_sd[N_EDGES];                      // sorted dst

// ---------------------------------------------------------------------------
__global__ void k_init() {
    int i = blockIdx.x * blockDim.x + threadIdx.x;
    if (i < N_NODES * 64) g_agg[i] = 0.f;
    if (i < N_NODES) { g_deg[i] = 0.f; g_cnt[i] = 0; g_cur[i] = 0; }
}

__global__ void k_zero_agg() {
    int i = blockIdx.x * blockDim.x + threadIdx.x;
    if (i < N_NODES * 64) g_agg[i] = 0.f;
}

__global__ void k_hist(const int* __restrict__ ei) {
    int e = blockIdx.x * blockDim.x + threadIdx.x;
    if (e >= N_EDGES) return;
    atomicAdd(&g_cnt[ei[e]], 1);
    atomicAdd(&g_deg[ei[N_EDGES + e]], 1.f);
}

__global__ void k_scan() {
    __shared__ int s[1024];
    __shared__ int carry;
    int tid = threadIdx.x;
    if (tid == 0) carry = 0;
    __syncthreads();
    for (int base = 0; base < N_NODES; base += 1024) {
        int i = base + tid;
        int v = (i < N_NODES) ? g_cnt[i] : 0;
        s[tid] = v;
        __syncthreads();
        for (int d = 1; d < 1024; d <<= 1) {
            int t = (tid >= d) ? s[tid - d] : 0;
            __syncthreads();
            s[tid] += t;
            __syncthreads();
        }
        if (i < N_NODES) g_off[i] = s[tid] - v + carry;
        __syncthreads();
        if (tid == 0) carry += s[1023];
        __syncthreads();
    }
}

__global__ void k_scatter(const int* __restrict__ ei) {
    int e = blockIdx.x * blockDim.x + threadIdx.x;
    if (e >= N_EDGES) return;
    int src = ei[e];
    int pos = g_off[src] + atomicAdd(&g_cur[src], 1);
    g_se[pos] = e;
    g_sd[pos] = ei[N_EDGES + e];
}

// ---- fp16 split conversions ------------------------------------------------
template <int CIN>
__global__ void k_conv_X(const float* __restrict__ X) {
    int idx = blockIdx.x * blockDim.x + threadIdx.x;
    if (idx >= N_PAD * CIN) return;
    int n = idx / CIN;
    float v = (n < N_NODES) ? X[idx] : 0.f;
    __half h = __float2half(v);
    g_Xh[idx] = h;
    g_Xl[idx] = __float2half(v - __half2float(h));
}

// W2 [64, CIN*64] -> B [CIN, 4096] permuted: B[i, m*64+o] = W2[m, i*64+o]
template <int CIN>
__global__ void k_conv_B(const float* __restrict__ W2) {
    int idx = blockIdx.x * blockDim.x + threadIdx.x;
    if (idx >= CIN * 4096) return;
    int i = idx >> 12;
    int c = idx & 4095;
    int m = c >> 6, o = c & 63;
    float v = W2[(size_t)m * (CIN * 64) + i * 64 + o];
    __half h = __float2half(v);
    g_Bh[idx] = h;
    g_Bl[idx] = __float2half(v - __half2float(h));
}

// h[e,j] = relu(b1[j] + sum_k ea[e,k]*w1[k,j])  -> fp16
__global__ void k_edge_hidden(const float* __restrict__ ea,
                              const float* __restrict__ w1,
                              const float* __restrict__ b1) {
    int idx = blockIdx.x * blockDim.x + threadIdx.x;
    if (idx >= N_EDGES * 64) return;
    int e = idx >> 6, j = idx & 63;
    const float* a = ea + (size_t)e * 4;
    float v = b1[j];
#pragma unroll
    for (int k = 0; k < 4; ++k) v = fmaf(a[k], w1[k * 64 + j], v);
    g_h[idx] = __float2half(fmaxf(v, 0.f));
}

// ---- G = X @ B via HMMA, persistent-B, smem epilogue (proven wmma4) --------
template <int K>
__global__ void __launch_bounds__(256) k_gemm_wmma4() {
    extern __shared__ __align__(16) unsigned char smem_raw[];
    __half* Bsh = (__half*)smem_raw;
    __half* Bsl = Bsh + K * 64;
    float*  Cs  = (float*)(Bsl + K * 64);     // 8 warps * 16*72 fp32

    const int tid  = threadIdx.x;
    const int col0 = blockIdx.x * 64;
    const int row_start = blockIdx.y * (N_PAD / GY);

    for (int i = tid; i < K * 8; i += 256) {
        int k = i >> 3, p = i & 7;
        ((uint4*)Bsh)[i] = *(const uint4*)(g_Bh + (size_t)k * 4096 + col0 + p * 8);
        ((uint4*)Bsl)[i] = *(const uint4*)(g_Bl + (size_t)k * 4096 + col0 + p * 8);
    }
    __syncthreads();

    const int w    = tid >> 5;
    const int lane = tid & 31;
    float* cw = Cs + w * (16 * 72);

    for (int r = row_start + w * 16; r < row_start + (N_PAD / GY); r += 128) {
        wmma::fragment<wmma::accumulator, 16, 16, 16, float> acc[4];
#pragma unroll
        for (int t = 0; t < 4; ++t) wmma::fill_fragment(acc[t], 0.f);

#pragma unroll
        for (int kc = 0; kc < K; kc += 16) {
            wmma::fragment<wmma::matrix_a, 16, 16, 16, __half, wmma::row_major> ah, al;
            wmma::load_matrix_sync(ah, g_Xh + (size_t)r * K + kc, K);
            wmma::load_matrix_sync(al, g_Xl + (size_t)r * K + kc, K);
#pragma unroll
            for (int t = 0; t < 4; ++t) {
                wmma::fragment<wmma::matrix_b, 16, 16, 16, __half, wmma::row_major> bh, bl;
                wmma::load_matrix_sync(bh, Bsh + kc * 64 + t * 16, 64);
                wmma::load_matrix_sync(bl, Bsl + kc * 64 + t * 16, 64);
                wmma::mma_sync(acc[t], ah, bh, acc[t]);
                wmma::mma_sync(acc[t], ah, bl, acc[t]);
                wmma::mma_sync(acc[t], al, bh, acc[t]);
            }
        }
#pragma unroll
        for (int t = 0; t < 4; ++t)
            wmma::store_matrix_sync(cw + t * 16, acc[t], 72, wmma::mem_row_major);
        __syncwarp();
#pragma unroll
        for (int rr = 0; rr < 16; ++rr) {
            float2 v = *(const float2*)&cw[rr * 72 + 2 * lane];
            ((__half2*)(g_Gh + (size_t)(r + rr) * 4096 + col0))[lane] =
                __floats2half2_rn(v.x, v.y);
        }
        __syncwarp();
    }
}

// XB[n,o] = sum_i X[n,i] * b2[i*64 + o]
template <int CIN>
__global__ void k_xb(const float* __restrict__ X, const float* __restrict__ b2) {
    int idx = blockIdx.x * blockDim.x + threadIdx.x;
    if (idx >= N_NODES * 64) return;
    int n = idx >> 6, o = idx & 63;
    const float* xr = X + (size_t)n * CIN;
    float v = 0.f;
#pragma unroll
    for (int i = 0; i < CIN; ++i) v = fmaf(xr[i], b2[i * 64 + o], v);
    g_XB[idx] = v;
}

// ---- edge messages via HMMA: one warp per src node -------------------------
// msg block = H_n (<=16 edges x 64) @ G_n (64x64), fp32 accum, then predicated
// atomic scatter to agg[dst] per real row, folding XB[src] per element.
// Accumulator lane map (validated R13): x0,x1->(l/4,(l%4)*2); x2,x3->row+8;
// x4..x7->col+8.
__global__ void __launch_bounds__(256) k_edge_msg3() {
    __shared__ __align__(16) __half Asl[8][16 * 64];
    const int wid  = threadIdx.x >> 5;
    const int lane = threadIdx.x & 31;
    const int n = blockIdx.x * 8 + wid;
    if (n >= N_NODES) return;
    const int beg = g_off[n];
    const int end = (n + 1 < N_NODES) ? g_off[n + 1] : N_EDGES;
    if (beg == end) return;

    const __half* Gn = g_Gh + (size_t)n * 4096;
    const float*  XBn = g_XB + n * 64;
    __half* Aw = Asl[wid];

    const int r0 = lane >> 2;          // 0..7
    const int c0 = (lane & 3) * 2;     // 0,2,4,6

    for (int g = beg; g < end; g += 16) {
        const int cnt = min(16, end - g);
        // stage up to 16 h-rows (128B each) into the warp's smem slab
#pragma unroll
        for (int q = 0; q < 4; ++q) {
            int idx = lane + q * 32;           // 0..127
            int row = idx >> 3, part = idx & 7;
            uint4 v = make_uint4(0u, 0u, 0u, 0u);
            if (row < cnt) {
                int e = g_se[g + row];
                v = *(const uint4*)(g_h + (size_t)e * 64 + part * 8);
            }
            *(uint4*)(Aw + row * 64 + part * 8) = v;
        }
        __syncwarp();

        wmma::fragment<wmma::accumulator, 16, 16, 16, float> acc[4];
#pragma unroll
        for (int t = 0; t < 4; ++t) wmma::fill_fragment(acc[t], 0.f);
#pragma unroll
        for (int kc = 0; kc < 4; ++kc) {
            wmma::fragment<wmma::matrix_a, 16, 16, 16, __half, wmma::row_major> af;
            wmma::load_matrix_sync(af, Aw + kc * 16, 64);
#pragma unroll
            for (int t = 0; t < 4; ++t) {
                wmma::fragment<wmma::matrix_b, 16, 16, 16, __half, wmma::row_major> bf;
                wmma::load_matrix_sync(bf, Gn + (size_t)kc * 16 * 64 + t * 16, 64);
                wmma::mma_sync(acc[t], af, bf, acc[t]);
            }
        }
        __syncwarp();

        const int s0 = r0, s1 = r0 + 8;
        const bool v0 = s0 < cnt, v1 = s1 < cnt;
        const int d0 = v0 ? g_sd[g + s0] * 64 : 0;
        const int d1 = v1 ? g_sd[g + s1] * 64 : 0;
#pragma unroll
        for (int t = 0; t < 4; ++t) {
            const int cA = t * 16 + c0;
            const float xa0 = XBn[cA],     xa1 = XBn[cA + 1];
            const float xb0 = XBn[cA + 8], xb1 = XBn[cA + 9];
            if (v0) {
                atomicAdd(&g_agg[d0 + cA],     acc[t].x[0] + xa0);
                atomicAdd(&g_agg[d0 + cA + 1], acc[t].x[1] + xa1);
                atomicAdd(&g_agg[d0 + cA + 8], acc[t].x[4] + xb0);
                atomicAdd(&g_agg[d0 + cA + 9], acc[t].x[5] + xb1);
            }
            if (v1) {
                atomicAdd(&g_agg[d1 + cA],     acc[t].x[2] + xa0);
                atomicAdd(&g_agg[d1 + cA + 1], acc[t].x[3] + xa1);
                atomicAdd(&g_agg[d1 + cA + 8], acc[t].x[6] + xb0);
                atomicAdd(&g_agg[d1 + cA + 9], acc[t].x[7] + xb1);
            }
        }
    }
}

// out[n,o] = relu(agg/max(deg,1) + x@root + bias)
template <int CIN>
__global__ void k_finalize(const float* __restrict__ Xin,
                           const float* __restrict__ root,
                           const float* __restrict__ bias,
                           float* __restrict__ out) {
    int idx = blockIdx.x * blockDim.x + threadIdx.x;
    if (idx >= N_NODES * 64) return;
    int n = idx >> 6, o = idx & 63;
    float inv = 1.f / fmaxf(g_deg[n], 1.f);
    float v = g_agg[idx] * inv + bias[o];
    const float* xr = Xin + (size_t)n * CIN;
#pragma unroll 8
    for (int i = 0; i < CIN; ++i) v = fmaf(xr[i], root[i * 64 + o], v);
    out[idx] = fmaxf(v, 0.f);
}

// readout: warp per node
__global__ void k_readout(const float* __restrict__ w1, const float* __restrict__ b1,
                          const float* __restrict__ w2, const float* __restrict__ b2,
                          float* __restrict__ out) {
    int warp = (blockIdx.x * blockDim.x + threadIdx.x) >> 5;
    int lane = threadIdx.x & 31;
    if (warp >= N_NODES) return;
    const float* zr = g_z + (size_t)warp * 64;
    float z0 = zr[lane], z1 = zr[lane + 32];
    float p[8];
#pragma unroll
    for (int j = 0; j < 8; ++j)
        p[j] = z0 * w1[lane * 8 + j] + z1 * w1[(lane + 32) * 8 + j];
    const unsigned FULL = 0xffffffffu;
#pragma unroll
    for (int off = 16; off; off >>= 1)
#pragma unroll
        for (int j = 0; j < 8; ++j) p[j] += __shfl_down_sync(FULL, p[j], off);
    if (lane == 0) {
        float r = b2[0];
#pragma unroll
        for (int j = 0; j < 8; ++j) r += fmaxf(p[j] + b1[j], 0.f) * w2[j];
        out[warp] = r;
    }
}

// ---------------------------------------------------------------------------
extern "C" void kernel_launch(void* const* d_in, const int* in_sizes, int n_in,
                              void* d_out, int out_size) {
    const float* x      = (const float*)d_in[0];
    const int*   ei     = (const int*)d_in[1];     // int32 (jax x64 disabled)
    const float* ea     = (const float*)d_in[2];
    const float* nn1_w1 = (const float*)d_in[3];
    const float* nn1_b1 = (const float*)d_in[4];
    const float* nn1_w2 = (const float*)d_in[5];
    const float* nn1_b2 = (const float*)d_in[6];
    const float* root1  = (const float*)d_in[7];
    const float* bias1  = (const float*)d_in[8];
    const float* nn2_w1 = (const float*)d_in[9];
    const float* nn2_b1 = (const float*)d_in[10];
    const float* nn2_w2 = (const float*)d_in[11];
    const float* nn2_b2 = (const float*)d_in[12];
    const float* root2  = (const float*)d_in[13];
    const float* bias2  = (const float*)d_in[14];
    const float* lin1_w = (const float*)d_in[15];
    const float* lin1_b = (const float*)d_in[16];
    const float* lin2_w = (const float*)d_in[17];
    const float* lin2_b = (const float*)d_in[18];
    float* out = (float*)d_out;

    float* d_y = nullptr; float* d_z = nullptr;
    cudaGetSymbolAddress((void**)&d_y, g_y);
    cudaGetSymbolAddress((void**)&d_z, g_z);

    const int SMEM1 = CIN1 * 64 * 2 * 2 + 8 * 16 * 72 * 4;   // 40960
    const int SMEM2 = HID  * 64 * 2 * 2 + 8 * 16 * 72 * 4;   // 53248
    cudaFuncSetAttribute(k_gemm_wmma4<CIN1>,
                         cudaFuncAttributeMaxDynamicSharedMemorySize, SMEM1);
    cudaFuncSetAttribute(k_gemm_wmma4<HID>,
                         cudaFuncAttributeMaxDynamicSharedMemorySize, SMEM2);

    const int T = 256;
    const int bNO  = (N_NODES * 64 + T - 1) / T;
    const int bE   = (N_EDGES + T - 1) / T;
    const int bEH  = (N_EDGES * 64 + T - 1) / T;
    const int bMSG = (N_NODES + 7) / 8;            // warp per src node
    const int bRD  = (N_NODES * 32 + T - 1) / T;
    dim3 gW(64, GY);

    // ---- sort edges by src (+ histograms) ----
    k_init<<<bNO, T>>>();
    k_hist<<<bE, T>>>(ei);
    k_scan<<<1, 1024>>>();
    k_scatter<<<bE, T>>>(ei);

    // ---- layer 1 (cin = 16) ----
    k_conv_B<CIN1><<<(CIN1 * 4096 + T - 1) / T, T>>>(nn1_w2);
    k_conv_X<CIN1><<<(N_PAD * CIN1 + T - 1) / T, T>>>(x);
    k_gemm_wmma4<CIN1><<<gW, 256, SMEM1>>>();
    k_edge_hidden<<<bEH, T>>>(ea, nn1_w1, nn1_b1);
    k_xb<CIN1><<<bNO, T>>>(x, nn1_b2);
    k_edge_msg3<<<bMSG, T>>>();
    k_finalize<CIN1><<<bNO, T>>>(x, root1, bias1, d_y);

    // ---- layer 2 (cin = 64) ----
    k_zero_agg<<<bNO, T>>>();
    k_conv_B<HID><<<(HID * 4096 + T - 1) / T, T>>>(nn2_w2);
    k_conv_X<HID><<<(N_PAD * HID + T - 1) / T, T>>>(d_y);
    k_edge_hidden<<<bEH, T>>>(ea, nn2_w1, nn2_b1);
    k_gemm_wmma4<HID><<<gW, 256, SMEM2>>>();
    k_xb<HID><<<bNO, T>>>(d_y, nn2_b2);
    k_edge_msg3<<<bMSG, T>>>();
    k_finalize<HID><<<bNO, T>>>(d_y, root2, bias2, d_z);

    // ---- readout ----
    k_readout<<<bRD, T>>>(lin1_w, lin1_b, lin2_w, lin2_b, out);
}